// round 6
// baseline (speedup 1.0000x reference)
#include <cuda_runtime.h>

#define T_NO 200
#define SUB  16
#define E_NO 2000
#define I_NO 500
#define TD   20000
#define CB   16
#define CTL  128

// ---------------- scratch (static device globals; no allocation) -------------
__device__ float g_syn_e[TD * SUB];
__device__ float g_syn_i[TD * SUB];
__device__ float g_syn[TD * SUB];   // filt_e + filt_i + Theta (folded)
__device__ int   g_asn_e[E_NO];
__device__ int   g_asn_i[I_NO];
__device__ float g_ek[SUB * T_NO];
__device__ float g_ik[SUB * T_NO];
__device__ float g_sk[SUB * T_NO];
__device__ float g_hk[SUB * T_NO];
__device__ float g_B[SUB * SUB];    // C_den[s][k] * A_k   (spk IIR injection mix)
__device__ float g_spkc[3 * SUB];   // r, 2r, -r^2 per subunit

// ---------------- filter precompute + neuron->subunit assignment -------------
__global__ void k_prep(const float* __restrict__ C_syn_e,
                       const float* __restrict__ C_syn_i,
                       const float* __restrict__ C_den,
                       const float* __restrict__ Te, const float* __restrict__ Ti,
                       const float* __restrict__ We, const float* __restrict__ Wi,
                       const float* __restrict__ De, const float* __restrict__ Di,
                       const float* __restrict__ Tspk, const float* __restrict__ Wspk,
                       const float* __restrict__ Whist,
                       float* __restrict__ out_filt)
{
    int tid = threadIdx.x;
    for (int e = tid; e < E_NO; e += blockDim.x) {
        int a = 0;
        for (int s = 0; s < SUB; s++)
            if (C_syn_e[s * E_NO + e] > 0.5f) a = s;
        g_asn_e[e] = a;
    }
    for (int i = tid; i < I_NO; i += blockDim.x) {
        int a = 0;
        for (int s = 0; s < SUB; s++)
            if (C_syn_i[s * I_NO + i] > 0.5f) a = s;
        g_asn_i[i] = a;
    }
    // spk IIR constants: sk[j] = A * j * r^j, A = e^(W - Tau), r = e^(-1/e^Tau)
    for (int s = tid; s < SUB; s += blockDim.x) {
        float r = expf(-1.0f / expf(Tspk[s]));
        g_spkc[s]          = r;
        g_spkc[SUB + s]    = 2.0f * r;
        g_spkc[2 * SUB + s] = -r * r;
    }
    for (int idx = tid; idx < SUB * SUB; idx += blockDim.x) {
        int k = idx & 15;
        float A = expf(Wspk[k] - Tspk[k]);
        g_B[idx] = C_den[idx] * A;
    }
    const float PI = 3.14159265358979323846f;
    for (int idx = tid; idx < SUB * T_NO; idx += blockDim.x) {
        int s   = idx / T_NO;
        int tau = idx % T_NO;
        float t = (float)tau;

        float te  = fmaxf(t - expf(De[s]), 0.0f);
        float tte = te / expf(Te[s]);
        float ek  = tte * expf(-tte) * expf(We[s]);

        float ti_ = fmaxf(t - expf(Di[s]), 0.0f);
        float tti = ti_ / expf(Ti[s]);
        float ik  = -tti * expf(-tti) * expf(Wi[s]);

        float tts = t / expf(Tspk[s]);
        float sk  = tts * expf(-tts) * expf(Wspk[s]);

        float raw = 4.0f * logf(t + 1.0f);
        float hk  = 0.0f;
        for (int b = 0; b < CB; b++) {
            float phi = (PI * 0.5f) * (float)b;
            float v   = 0.5f * cosf(raw - phi) + 0.5f;
            if (raw < phi - PI || raw > phi + PI) v = 0.0f;
            hk += Whist[s * CB + b] * v;
        }
        g_ek[idx] = ek; g_ik[idx] = ik; g_sk[idx] = sk; g_hk[idx] = hk;

        out_filt[(s)      * T_NO + tau] = ek;
        out_filt[(16 + s) * T_NO + tau] = ik;
        out_filt[(32 + s) * T_NO + tau] = sk;
        out_filt[(48 + s) * T_NO + tau] = hk;
    }
}

// ---------------- one-hot pooling: exact integer counts ----------------------
__global__ void k_syn(const float* __restrict__ Se, const float* __restrict__ Si)
{
    __shared__ float be[SUB], bi[SUB];
    int t = blockIdx.x, tid = threadIdx.x;
    if (tid < SUB) { be[tid] = 0.0f; bi[tid] = 0.0f; }
    __syncthreads();
    for (int e = tid; e < E_NO; e += blockDim.x) {
        float v = Se[(size_t)t * E_NO + e];
        if (v != 0.0f) atomicAdd(&be[g_asn_e[e]], v);
    }
    for (int i = tid; i < I_NO; i += blockDim.x) {
        float v = Si[(size_t)t * I_NO + i];
        if (v != 0.0f) atomicAdd(&bi[g_asn_i[i]], v);
    }
    __syncthreads();
    if (tid < SUB) {
        g_syn_e[t * SUB + tid] = be[tid];
        g_syn_i[t * SUB + tid] = bi[tid];
    }
}

// ---------------- causal 200-tap depthwise conv (Theta folded in) ------------
__global__ void k_conv(const float* __restrict__ Theta)
{
    __shared__ float sek[SUB * 201];
    __shared__ float sik[SUB * 201];
    int tid = threadIdx.x;
    for (int idx = tid; idx < SUB * T_NO; idx += blockDim.x) {
        int s = idx / T_NO, d = idx % T_NO;
        sek[s * 201 + d] = g_ek[idx];
        sik[s * 201 + d] = g_ik[idx];
    }
    __syncthreads();

    int t0  = blockIdx.x * CTL;
    int s   = tid & 15;
    int tl0 = tid >> 4;
    float th = Theta[s];
    for (int j = 0; j < CTL / 16; j++) {
        int t = t0 + tl0 + j * 16;
        if (t < TD) {
            float acc = th;
            const float* ke = &sek[s * 201];
            const float* ki = &sik[s * 201];
            #pragma unroll 4
            for (int d = 1; d <= T_NO; d++) {
                int u = t - d;
                float ve = (u >= 0) ? __ldg(&g_syn_e[u * SUB + s]) : 0.0f;
                float vi = (u >= 0) ? __ldg(&g_syn_i[u * SUB + s]) : 0.0f;
                acc += ve * ke[d - 1] + vi * ki[d - 1];
            }
            g_syn[t * SUB + s] = acc;
        }
    }
}

// ---------------- the sequential threshold scan (critical path) --------------
// Warp 0 = conductor: spk path as exact per-subunit 2-state IIR in registers
// (spk_kern is an alpha function: sk[j] = A*j*r^j), C_den mix via 16 register
// shuffles, hist lags d=1,2 from register spike history. Warps 1..16 = hist
// gather for subunit (wid-1), lags d=3..200, read from a 16-bit spike-mask
// ring (one uint32 per step, duplicated for wrap-free indexing): 7 broadcast
// LDS.32 + bit-select adds + 5-level butterfly. Helpers at step t produce
// H[d>=3] for step t+1 from masks <= t-1 (2 steps of slack), published in a
// parity double-buffered slot. ONE __syncthreads per step; conductor and
// helpers run concurrently.
__global__ void __launch_bounds__(544, 1)
k_scan(float* __restrict__ out)
{
    __shared__ unsigned mring[512];       // spike masks, [t&255] and +256 dup
    __shared__ float Hbuf[2][SUB];        // parity-buffered hist(d>=3) per sub

    int tid = threadIdx.x, wid = tid >> 5, lane = tid & 31;

    for (int i = tid; i < 512; i += blockDim.x) mring[i] = 0u;
    if (tid < 32) ((float*)Hbuf)[tid] = 0.0f;

    if (wid == 0) {
        // ---------------- conductor ----------------
        int s = lane & 15;                 // lanes 16-31 mirror (ballot-masked)
        float Bm[16];
        #pragma unroll
        for (int k = 0; k < 16; k++) Bm[k] = g_B[s * SUB + k];
        float hk0 = g_hk[s * T_NO + 0];
        float hk1 = g_hk[s * T_NO + 1];
        float r    = g_spkc[s];
        float twor = g_spkc[SUB + s];
        float nr2  = g_spkc[2 * SUB + s];

        float y0 = 0.0f, y1 = 0.0f;        // y[t-2], y[t-1]
        float xm1 = 0.0f, xm2 = 0.0f;      // spikes at t-1, t-2
        float syn0 = __ldg(&g_syn[0 * SUB + s]);
        float syn1 = __ldg(&g_syn[1 * SUB + s]);
        float syn2 = __ldg(&g_syn[2 * SUB + s]);

        __syncthreads();

        for (int t = 0; t < TD; t++) {
            // C_den mix of spk IIR states (uses y[t-1], register-only)
            float m0 = 0.f, m1 = 0.f, m2 = 0.f, m3 = 0.f;
            #pragma unroll
            for (int k = 0; k < 16; k += 4) {
                m0 = fmaf(Bm[k],     __shfl_sync(0xffffffffu, y1, k),     m0);
                m1 = fmaf(Bm[k + 1], __shfl_sync(0xffffffffu, y1, k + 1), m1);
                m2 = fmaf(Bm[k + 2], __shfl_sync(0xffffffffu, y1, k + 2), m2);
                m3 = fmaf(Bm[k + 3], __shfl_sync(0xffffffffu, y1, k + 3), m3);
            }
            float H = (lane < 16) ? Hbuf[t & 1][s] : 0.0f;
            float acc = ((m0 + m1) + (m2 + m3)) + H
                      + fmaf(hk0, xm1, fmaf(hk1, xm2, syn0));
            // spk IIR advance: y[t] = 2r y[t-1] - r^2 y[t-2] + r x[t-1]
            float yn = fmaf(twor, y1, fmaf(nr2, y0, r * xm1));
            y0 = y1; y1 = yn;

            float spk = (acc > 0.0f) ? 1.0f : 0.0f;
            unsigned mm = __ballot_sync(0xffffffffu, acc > 0.0f) & 0xFFFFu;
            if (lane == 0) {
                mring[t & 255]         = mm;
                mring[(t & 255) + 256] = mm;
            }
            if (lane < 16) {
                Hbuf[t & 1][s] = 0.0f;         // recycle slot for step t+2
                out[t * SUB + s] = spk;
            }
            xm2 = xm1; xm1 = spk;
            syn0 = syn1; syn1 = syn2;
            if (lane < 16 && t + 3 < TD) syn2 = __ldg(&g_syn[(t + 3) * SUB + s]);
            __syncthreads();
        }
    } else {
        // ---------------- hist gather helpers ----------------
        int s = wid - 1;
        // lane handles lags d = 3 + lane + 32k, k = 0..6 (zero-padded > 200)
        float wgt[7];
        #pragma unroll
        for (int k = 0; k < 7; k++) {
            int d = 3 + lane + 32 * k;
            wgt[k] = (d <= T_NO) ? g_hk[s * T_NO + d - 1] : 0.0f;
        }
        __syncthreads();

        for (int t = 0; t < TD; t++) {
            // H for step t+1: taps at times t-2-lane-32k (masks <= t-1 only)
            int b = 256 + ((t - 2 - lane) & 255);
            float a0 = 0.f, a1 = 0.f;
            #pragma unroll
            for (int k = 0; k < 7; k++) {
                unsigned w = mring[b - 32 * k];
                int sel = -(int)((w >> s) & 1u);
                float v = __int_as_float(__float_as_int(wgt[k]) & sel);
                if (k & 1) a1 += v; else a0 += v;
            }
            float v = a0 + a1;
            v += __shfl_xor_sync(0xffffffffu, v, 16);
            v += __shfl_xor_sync(0xffffffffu, v, 8);
            v += __shfl_xor_sync(0xffffffffu, v, 4);
            v += __shfl_xor_sync(0xffffffffu, v, 2);
            v += __shfl_xor_sync(0xffffffffu, v, 1);
            if (lane == 0) Hbuf[(t + 1) & 1][s] = v;
            __syncthreads();
        }
    }
}

// ---------------- launcher ---------------------------------------------------
extern "C" void kernel_launch(void* const* d_in, const int* in_sizes, int n_in,
                              void* d_out, int out_size)
{
    const float* S_e     = (const float*)d_in[0];
    const float* S_i     = (const float*)d_in[1];
    const float* C_den   = (const float*)d_in[2];
    const float* C_syn_e = (const float*)d_in[3];
    const float* C_syn_i = (const float*)d_in[4];
    const float* Tau_e   = (const float*)d_in[5];
    const float* Tau_i   = (const float*)d_in[6];
    const float* W_e     = (const float*)d_in[7];
    const float* W_i     = (const float*)d_in[8];
    const float* D_e     = (const float*)d_in[9];
    const float* D_i     = (const float*)d_in[10];
    const float* Tau_spk = (const float*)d_in[11];
    const float* W_spk   = (const float*)d_in[12];
    const float* W_hist  = (const float*)d_in[13];
    const float* Theta   = (const float*)d_in[14];
    float* out = (float*)d_out;

    k_prep<<<1, 256>>>(C_syn_e, C_syn_i, C_den, Tau_e, Tau_i, W_e, W_i,
                       D_e, D_i, Tau_spk, W_spk, W_hist,
                       out + (size_t)TD * SUB);
    k_syn<<<TD, 128>>>(S_e, S_i);
    k_conv<<<(TD + CTL - 1) / CTL, 256>>>(Theta);
    k_scan<<<1, 544>>>(out);
}

// round 7
// speedup vs baseline: 1.4756x; 1.4756x over previous
#include <cuda_runtime.h>

#define T_NO 200
#define SUB  16
#define E_NO 2000
#define I_NO 500
#define TD   20000
#define CB   16
#define CTL  128

// ---------------- scratch (static device globals; no allocation) -------------
__device__ float g_syn_e[TD * SUB];
__device__ float g_syn_i[TD * SUB];
__device__ float g_syn[TD * SUB];   // filt_e + filt_i + Theta (folded)
__device__ int   g_asn_e[E_NO];
__device__ int   g_asn_i[I_NO];
__device__ float g_ek[SUB * T_NO];
__device__ float g_ik[SUB * T_NO];
__device__ float g_sk[SUB * T_NO];
__device__ float g_hk[SUB * T_NO];
__device__ float g_B[SUB * SUB];    // C_den[s][k] * A_k   (spk IIR injection mix)
__device__ float g_spkc[3 * SUB];   // r, 2r, -r^2 per subunit

// ---------------- filter precompute + neuron->subunit assignment -------------
__global__ void k_prep(const float* __restrict__ C_syn_e,
                       const float* __restrict__ C_syn_i,
                       const float* __restrict__ C_den,
                       const float* __restrict__ Te, const float* __restrict__ Ti,
                       const float* __restrict__ We, const float* __restrict__ Wi,
                       const float* __restrict__ De, const float* __restrict__ Di,
                       const float* __restrict__ Tspk, const float* __restrict__ Wspk,
                       const float* __restrict__ Whist,
                       float* __restrict__ out_filt)
{
    int tid = threadIdx.x;
    for (int e = tid; e < E_NO; e += blockDim.x) {
        int a = 0;
        for (int s = 0; s < SUB; s++)
            if (C_syn_e[s * E_NO + e] > 0.5f) a = s;
        g_asn_e[e] = a;
    }
    for (int i = tid; i < I_NO; i += blockDim.x) {
        int a = 0;
        for (int s = 0; s < SUB; s++)
            if (C_syn_i[s * I_NO + i] > 0.5f) a = s;
        g_asn_i[i] = a;
    }
    // spk IIR constants: sk[j] = A * j * r^j, A = e^(W - Tau), r = e^(-1/e^Tau)
    for (int s = tid; s < SUB; s += blockDim.x) {
        float r = expf(-1.0f / expf(Tspk[s]));
        g_spkc[s]          = r;
        g_spkc[SUB + s]    = 2.0f * r;
        g_spkc[2 * SUB + s] = -r * r;
    }
    for (int idx = tid; idx < SUB * SUB; idx += blockDim.x) {
        int k = idx & 15;
        float A = expf(Wspk[k] - Tspk[k]);
        g_B[idx] = C_den[idx] * A;
    }
    const float PI = 3.14159265358979323846f;
    for (int idx = tid; idx < SUB * T_NO; idx += blockDim.x) {
        int s   = idx / T_NO;
        int tau = idx % T_NO;
        float t = (float)tau;

        float te  = fmaxf(t - expf(De[s]), 0.0f);
        float tte = te / expf(Te[s]);
        float ek  = tte * expf(-tte) * expf(We[s]);

        float ti_ = fmaxf(t - expf(Di[s]), 0.0f);
        float tti = ti_ / expf(Ti[s]);
        float ik  = -tti * expf(-tti) * expf(Wi[s]);

        float tts = t / expf(Tspk[s]);
        float sk  = tts * expf(-tts) * expf(Wspk[s]);

        float raw = 4.0f * logf(t + 1.0f);
        float hk  = 0.0f;
        for (int b = 0; b < CB; b++) {
            float phi = (PI * 0.5f) * (float)b;
            float v   = 0.5f * cosf(raw - phi) + 0.5f;
            if (raw < phi - PI || raw > phi + PI) v = 0.0f;
            hk += Whist[s * CB + b] * v;
        }
        g_ek[idx] = ek; g_ik[idx] = ik; g_sk[idx] = sk; g_hk[idx] = hk;

        out_filt[(s)      * T_NO + tau] = ek;
        out_filt[(16 + s) * T_NO + tau] = ik;
        out_filt[(32 + s) * T_NO + tau] = sk;
        out_filt[(48 + s) * T_NO + tau] = hk;
    }
}

// ---------------- one-hot pooling: exact integer counts ----------------------
__global__ void k_syn(const float* __restrict__ Se, const float* __restrict__ Si)
{
    __shared__ float be[SUB], bi[SUB];
    int t = blockIdx.x, tid = threadIdx.x;
    if (tid < SUB) { be[tid] = 0.0f; bi[tid] = 0.0f; }
    __syncthreads();
    for (int e = tid; e < E_NO; e += blockDim.x) {
        float v = Se[(size_t)t * E_NO + e];
        if (v != 0.0f) atomicAdd(&be[g_asn_e[e]], v);
    }
    for (int i = tid; i < I_NO; i += blockDim.x) {
        float v = Si[(size_t)t * I_NO + i];
        if (v != 0.0f) atomicAdd(&bi[g_asn_i[i]], v);
    }
    __syncthreads();
    if (tid < SUB) {
        g_syn_e[t * SUB + tid] = be[tid];
        g_syn_i[t * SUB + tid] = bi[tid];
    }
}

// ---------------- causal 200-tap depthwise conv (Theta folded in) ------------
__global__ void k_conv(const float* __restrict__ Theta)
{
    __shared__ float sek[SUB * 201];
    __shared__ float sik[SUB * 201];
    int tid = threadIdx.x;
    for (int idx = tid; idx < SUB * T_NO; idx += blockDim.x) {
        int s = idx / T_NO, d = idx % T_NO;
        sek[s * 201 + d] = g_ek[idx];
        sik[s * 201 + d] = g_ik[idx];
    }
    __syncthreads();

    int t0  = blockIdx.x * CTL;
    int s   = tid & 15;
    int tl0 = tid >> 4;
    float th = Theta[s];
    for (int j = 0; j < CTL / 16; j++) {
        int t = t0 + tl0 + j * 16;
        if (t < TD) {
            float acc = th;
            const float* ke = &sek[s * 201];
            const float* ki = &sik[s * 201];
            #pragma unroll 4
            for (int d = 1; d <= T_NO; d++) {
                int u = t - d;
                float ve = (u >= 0) ? __ldg(&g_syn_e[u * SUB + s]) : 0.0f;
                float vi = (u >= 0) ? __ldg(&g_syn_i[u * SUB + s]) : 0.0f;
                acc += ve * ke[d - 1] + vi * ki[d - 1];
            }
            g_syn[t * SUB + s] = acc;
        }
    }
}

// ---------------- the sequential threshold scan (critical path) --------------
// Warp 0 = conductor: spk path as exact per-subunit 2-state IIR in registers
// (spk_kern is an alpha function: sk[j] = A*j*r^j), C_den mix via 16 register
// shuffles, hist lags d=1,2 from register spike history. Warps 1..16 = hist
// gather for subunit (wid-1), lags d=3..200, read from a 16-bit spike-mask
// ring (one uint32 per step, duplicated for wrap-free indexing): 7 broadcast
// LDS.32 + bit-select adds + 5-level butterfly. Helpers at step t produce
// H[d>=3] for step t+1 from masks <= t-1 (2 steps of slack), published in a
// parity double-buffered slot. ONE __syncthreads per step; conductor and
// helpers run concurrently.
__global__ void __launch_bounds__(544, 1)
k_scan(float* __restrict__ out)
{
    __shared__ unsigned mring[512];       // spike masks, [t&255] and +256 dup
    __shared__ float Hbuf[2][SUB];        // parity-buffered hist(d>=3) per sub

    int tid = threadIdx.x, wid = tid >> 5, lane = tid & 31;

    for (int i = tid; i < 512; i += blockDim.x) mring[i] = 0u;
    if (tid < 32) ((float*)Hbuf)[tid] = 0.0f;

    if (wid == 0) {
        // ---------------- conductor ----------------
        int s = lane & 15;                 // lanes 16-31 mirror (ballot-masked)
        float Bm[16];
        #pragma unroll
        for (int k = 0; k < 16; k++) Bm[k] = g_B[s * SUB + k];
        float hk0 = g_hk[s * T_NO + 0];
        float hk1 = g_hk[s * T_NO + 1];
        float r    = g_spkc[s];
        float twor = g_spkc[SUB + s];
        float nr2  = g_spkc[2 * SUB + s];

        float y0 = 0.0f, y1 = 0.0f;        // y[t-2], y[t-1]
        float xm1 = 0.0f, xm2 = 0.0f;      // spikes at t-1, t-2
        float syn0 = __ldg(&g_syn[0 * SUB + s]);
        float syn1 = __ldg(&g_syn[1 * SUB + s]);
        float syn2 = __ldg(&g_syn[2 * SUB + s]);

        __syncthreads();

        for (int t = 0; t < TD; t++) {
            // C_den mix of spk IIR states (uses y[t-1], register-only)
            float m0 = 0.f, m1 = 0.f, m2 = 0.f, m3 = 0.f;
            #pragma unroll
            for (int k = 0; k < 16; k += 4) {
                m0 = fmaf(Bm[k],     __shfl_sync(0xffffffffu, y1, k),     m0);
                m1 = fmaf(Bm[k + 1], __shfl_sync(0xffffffffu, y1, k + 1), m1);
                m2 = fmaf(Bm[k + 2], __shfl_sync(0xffffffffu, y1, k + 2), m2);
                m3 = fmaf(Bm[k + 3], __shfl_sync(0xffffffffu, y1, k + 3), m3);
            }
            float H = (lane < 16) ? Hbuf[t & 1][s] : 0.0f;
            float acc = ((m0 + m1) + (m2 + m3)) + H
                      + fmaf(hk0, xm1, fmaf(hk1, xm2, syn0));
            // spk IIR advance: y[t] = 2r y[t-1] - r^2 y[t-2] + r x[t-1]
            float yn = fmaf(twor, y1, fmaf(nr2, y0, r * xm1));
            y0 = y1; y1 = yn;

            float spk = (acc > 0.0f) ? 1.0f : 0.0f;
            unsigned mm = __ballot_sync(0xffffffffu, acc > 0.0f) & 0xFFFFu;
            if (lane == 0) {
                mring[t & 255]         = mm;
                mring[(t & 255) + 256] = mm;
            }
            if (lane < 16) {
                Hbuf[t & 1][s] = 0.0f;         // recycle slot for step t+2
                out[t * SUB + s] = spk;
            }
            xm2 = xm1; xm1 = spk;
            syn0 = syn1; syn1 = syn2;
            if (lane < 16 && t + 3 < TD) syn2 = __ldg(&g_syn[(t + 3) * SUB + s]);
            __syncthreads();
        }
    } else {
        // ---------------- hist gather helpers ----------------
        int s = wid - 1;
        // lane handles lags d = 3 + lane + 32k, k = 0..6 (zero-padded > 200)
        float wgt[7];
        #pragma unroll
        for (int k = 0; k < 7; k++) {
            int d = 3 + lane + 32 * k;
            wgt[k] = (d <= T_NO) ? g_hk[s * T_NO + d - 1] : 0.0f;
        }
        __syncthreads();

        for (int t = 0; t < TD; t++) {
            // H for step t+1: taps at times t-2-lane-32k (masks <= t-1 only)
            int b = 256 + ((t - 2 - lane) & 255);
            float a0 = 0.f, a1 = 0.f;
            #pragma unroll
            for (int k = 0; k < 7; k++) {
                unsigned w = mring[b - 32 * k];
                int sel = -(int)((w >> s) & 1u);
                float v = __int_as_float(__float_as_int(wgt[k]) & sel);
                if (k & 1) a1 += v; else a0 += v;
            }
            float v = a0 + a1;
            v += __shfl_xor_sync(0xffffffffu, v, 16);
            v += __shfl_xor_sync(0xffffffffu, v, 8);
            v += __shfl_xor_sync(0xffffffffu, v, 4);
            v += __shfl_xor_sync(0xffffffffu, v, 2);
            v += __shfl_xor_sync(0xffffffffu, v, 1);
            if (lane == 0) Hbuf[(t + 1) & 1][s] = v;
            __syncthreads();
        }
    }
}

// ---------------- launcher ---------------------------------------------------
extern "C" void kernel_launch(void* const* d_in, const int* in_sizes, int n_in,
                              void* d_out, int out_size)
{
    const float* S_e     = (const float*)d_in[0];
    const float* S_i     = (const float*)d_in[1];
    const float* C_den   = (const float*)d_in[2];
    const float* C_syn_e = (const float*)d_in[3];
    const float* C_syn_i = (const float*)d_in[4];
    const float* Tau_e   = (const float*)d_in[5];
    const float* Tau_i   = (const float*)d_in[6];
    const float* W_e     = (const float*)d_in[7];
    const float* W_i     = (const float*)d_in[8];
    const float* D_e     = (const float*)d_in[9];
    const float* D_i     = (const float*)d_in[10];
    const float* Tau_spk = (const float*)d_in[11];
    const float* W_spk   = (const float*)d_in[12];
    const float* W_hist  = (const float*)d_in[13];
    const float* Theta   = (const float*)d_in[14];
    float* out = (float*)d_out;

    k_prep<<<1, 256>>>(C_syn_e, C_syn_i, C_den, Tau_e, Tau_i, W_e, W_i,
                       D_e, D_i, Tau_spk, W_spk, W_hist,
                       out + (size_t)TD * SUB);
    k_syn<<<TD, 128>>>(S_e, S_i);
    k_conv<<<(TD + CTL - 1) / CTL, 256>>>(Theta);
    k_scan<<<1, 544>>>(out);
}

// round 8
// speedup vs baseline: 6.5889x; 4.4652x over previous
#include <cuda_runtime.h>

#define T_NO 200
#define SUB  16
#define E_NO 2000
#define I_NO 500
#define TD   20000
#define CB   16
#define CTL  128
#define NCH  2500          // TD/8 chunks

// smem layout (floats) for k_scan
#define RING0 0            // 16 rows x 513
#define LUT0  8208         // 2 x 256 x 16
#define PART0 16400        // 16 warps x 288
#define HB0   21008        // 2 x 8 x 17
#define SMF   21280

__device__ float g_syn_e[TD * SUB];
__device__ float g_syn_i[TD * SUB];
__device__ float g_syn[TD * SUB];     // conv + Theta folded
__device__ int   g_asn_e[E_NO];
__device__ int   g_asn_i[I_NO];
__device__ float g_ek[SUB * T_NO];
__device__ float g_ik[SUB * T_NO];
__device__ float g_sk[SUB * T_NO];
__device__ float g_hk[SUB * T_NO];
__device__ float g_B[SUB * SUB];      // C_den * A_k * r_k  (IIR injection)
__device__ float g_spkc[3 * SUB];     // r, 2r, -r^2

__global__ void k_prep(const float* __restrict__ C_syn_e,
                       const float* __restrict__ C_syn_i,
                       const float* __restrict__ C_den,
                       const float* __restrict__ Te, const float* __restrict__ Ti,
                       const float* __restrict__ We, const float* __restrict__ Wi,
                       const float* __restrict__ De, const float* __restrict__ Di,
                       const float* __restrict__ Tspk, const float* __restrict__ Wspk,
                       const float* __restrict__ Whist,
                       float* __restrict__ out_filt)
{
    int tid = threadIdx.x;
    for (int e = tid; e < E_NO; e += blockDim.x) {
        int a = 0;
        for (int s = 0; s < SUB; s++)
            if (C_syn_e[s * E_NO + e] > 0.5f) a = s;
        g_asn_e[e] = a;
    }
    for (int i = tid; i < I_NO; i += blockDim.x) {
        int a = 0;
        for (int s = 0; s < SUB; s++)
            if (C_syn_i[s * I_NO + i] > 0.5f) a = s;
        g_asn_i[i] = a;
    }
    for (int s = tid; s < SUB; s += blockDim.x) {
        float r = expf(-1.0f / expf(Tspk[s]));
        g_spkc[s] = r; g_spkc[SUB + s] = 2.0f * r; g_spkc[2 * SUB + s] = -r * r;
    }
    for (int idx = tid; idx < SUB * SUB; idx += blockDim.x) {
        int k = idx & 15;
        float r = expf(-1.0f / expf(Tspk[k]));
        g_B[idx] = C_den[idx] * expf(Wspk[k] - Tspk[k]) * r;
    }
    const float PI = 3.14159265358979323846f;
    for (int idx = tid; idx < SUB * T_NO; idx += blockDim.x) {
        int s = idx / T_NO, tau = idx % T_NO;
        float t = (float)tau;
        float te  = fmaxf(t - expf(De[s]), 0.0f);
        float tte = te / expf(Te[s]);
        float ek  = tte * expf(-tte) * expf(We[s]);
        float ti_ = fmaxf(t - expf(Di[s]), 0.0f);
        float tti = ti_ / expf(Ti[s]);
        float ik  = -tti * expf(-tti) * expf(Wi[s]);
        float tts = t / expf(Tspk[s]);
        float sk  = tts * expf(-tts) * expf(Wspk[s]);
        float raw = 4.0f * logf(t + 1.0f);
        float hk  = 0.0f;
        for (int b = 0; b < CB; b++) {
            float phi = (PI * 0.5f) * (float)b;
            float v   = 0.5f * cosf(raw - phi) + 0.5f;
            if (raw < phi - PI || raw > phi + PI) v = 0.0f;
            hk += Whist[s * CB + b] * v;
        }
        g_ek[idx] = ek; g_ik[idx] = ik; g_sk[idx] = sk; g_hk[idx] = hk;
        out_filt[(s)      * T_NO + tau] = ek;
        out_filt[(16 + s) * T_NO + tau] = ik;
        out_filt[(32 + s) * T_NO + tau] = sk;
        out_filt[(48 + s) * T_NO + tau] = hk;
    }
}

__global__ void k_syn(const float* __restrict__ Se, const float* __restrict__ Si)
{
    __shared__ float be[SUB], bi[SUB];
    int t = blockIdx.x, tid = threadIdx.x;
    if (tid < SUB) { be[tid] = 0.0f; bi[tid] = 0.0f; }
    __syncthreads();
    for (int e = tid; e < E_NO; e += blockDim.x) {
        float v = Se[(size_t)t * E_NO + e];
        if (v != 0.0f) atomicAdd(&be[g_asn_e[e]], v);
    }
    for (int i = tid; i < I_NO; i += blockDim.x) {
        float v = Si[(size_t)t * I_NO + i];
        if (v != 0.0f) atomicAdd(&bi[g_asn_i[i]], v);
    }
    __syncthreads();
    if (tid < SUB) {
        g_syn_e[t * SUB + tid] = be[tid];
        g_syn_i[t * SUB + tid] = bi[tid];
    }
}

__global__ void k_conv(const float* __restrict__ Theta)
{
    __shared__ float sek[SUB * 201];
    __shared__ float sik[SUB * 201];
    int tid = threadIdx.x;
    for (int idx = tid; idx < SUB * T_NO; idx += blockDim.x) {
        int s = idx / T_NO, d = idx % T_NO;
        sek[s * 201 + d] = g_ek[idx];
        sik[s * 201 + d] = g_ik[idx];
    }
    __syncthreads();
    int t0 = blockIdx.x * CTL, s = tid & 15, tl0 = tid >> 4;
    float th = Theta[s];
    for (int j = 0; j < CTL / 16; j++) {
        int t = t0 + tl0 + j * 16;
        if (t < TD) {
            float acc = th;
            const float* ke = &sek[s * 201];
            const float* ki = &sik[s * 201];
            #pragma unroll 4
            for (int d = 1; d <= T_NO; d++) {
                int u = t - d;
                float ve = (u >= 0) ? __ldg(&g_syn_e[u * SUB + s]) : 0.0f;
                float vi = (u >= 0) ? __ldg(&g_syn_i[u * SUB + s]) : 0.0f;
                acc += ve * ke[d - 1] + vi * ki[d - 1];
            }
            g_syn[t * SUB + s] = acc;
        }
    }
}

// chunked scan: chunk=8 steps, ONE barrier per chunk.
// wid 0 = conductor (lane&15 = subunit): hist d=1..18 in regs, spk path as
// collapsed 2-state IIR with mask-LUT injection (2-step slack).
// 16 helper warps (subunit each): hist d=19..200 for NEXT chunk, 6 consecutive
// taps per lane, 13-float spike window, smem-transpose reduce.
__global__ void __launch_bounds__(640, 1) k_scan(float* __restrict__ out)
{
    extern __shared__ float sm[];
    int tid = threadIdx.x, wid = tid >> 5, lane = tid & 31;

    for (int i = tid; i < SMF; i += blockDim.x) sm[i] = 0.0f;
    __syncthreads();
    for (int idx = tid; idx < 8192; idx += blockDim.x) {
        int m = (idx >> 4) & 255, s = idx & 15, h = idx >> 12;
        float v = 0.0f;
        #pragma unroll
        for (int b = 0; b < 8; b++)
            if ((m >> b) & 1) v += g_B[s * SUB + 8 * h + b];
        sm[LUT0 + idx] = v;
    }

    if (wid == 0) {
        // ------------- conductor -------------
        int s = lane & 15;
        float hkr[18];
        #pragma unroll
        for (int i = 0; i < 18; i++) hkr[i] = g_hk[s * T_NO + i];
        float twor = g_spkc[SUB + s], nr2 = g_spkc[2 * SUB + s];
        float f[19];
        #pragma unroll
        for (int j = 0; j < 19; j++) f[j] = 0.0f;
        float z0 = 0.f, z1 = 0.f, lutA = 0.f, lutB = 0.f;
        float cur[8], nxt[8];
        #pragma unroll
        for (int l = 0; l < 8; l++) cur[l] = __ldg(&g_syn[l * SUB + s]);
        float* ringw = sm + RING0 + s * 513;
        const float* lut = sm + LUT0;

        for (int kc = 0; kc < NCH; kc++) {
            __syncthreads();
            int t0 = kc * 8, c0 = t0 & 255;
            const float* hrow = sm + HB0 + (kc & 1) * 136;
            float K[8];
            #pragma unroll
            for (int l = 0; l < 8; l++) K[l] = hrow[l * 17 + s] + cur[l];
            #pragma unroll
            for (int l = 0; l < 8; l++) {
                int tn = t0 + 8 + l;
                nxt[l] = (tn < TD) ? __ldg(&g_syn[tn * SUB + s]) : 0.0f;
            }
            #pragma unroll
            for (int l = 0; l < 8; l++) {
                float zn = fmaf(twor, z1, fmaf(nr2, z0, lutA));  // z(t-1)
                z0 = z1; z1 = zn; lutA = lutB;
                float P = 0.0f;
                #pragma unroll
                for (int j = 2; j <= 18; j++) P = fmaf(hkr[j - 1], f[j], P);
                float A = fmaf(hkr[0], f[1], P);
                float acc = (A + K[l]) + zn;
                bool pr = acc > 0.0f;
                unsigned mm = __ballot_sync(0xffffffffu, pr) & 0xFFFFu;
                float spkf = pr ? 1.0f : 0.0f;
                if (lane < 16) {
                    int c = c0 + l;
                    ringw[c] = spkf; ringw[c + 256] = spkf;
                    out[(t0 + l) * SUB + s] = spkf;
                }
                lutB = lut[(mm & 255u) * 16 + s] + lut[4096 + (mm >> 8) * 16 + s];
                #pragma unroll
                for (int j = 18; j >= 2; j--) f[j] = f[j - 1];
                f[1] = spkf;
            }
            #pragma unroll
            for (int l = 0; l < 8; l++) cur[l] = nxt[l];
        }
    } else if (wid != 8 && wid != 12 && wid != 16) {
        // ------------- helpers -------------
        int s = wid - 1 - (wid > 8) - (wid > 12) - (wid > 16);
        int d0 = 19 + 6 * lane;
        float w[6];
        #pragma unroll
        for (int j = 0; j < 6; j++) {
            int d = d0 + j;
            w[j] = (d <= T_NO) ? g_hk[s * T_NO + d - 1] : 0.0f;
        }
        const float* ringr = sm + RING0 + s * 513;
        float* pw = sm + PART0 + s * 288;
        int lq = lane & 7, q = lane >> 3;

        for (int kc = 0; kc < NCH; kc++) {
            __syncthreads();
            int t1 = kc * 8 + 8;
            int a0 = 256 + (t1 & 255) - d0 - 5;
            float xw[13];
            #pragma unroll
            for (int i = 0; i < 13; i++) xw[i] = ringr[a0 + i];
            float acc[8];
            #pragma unroll
            for (int l = 0; l < 8; l++) acc[l] = 0.0f;
            #pragma unroll
            for (int j = 0; j < 6; j++)
                #pragma unroll
                for (int l = 0; l < 8; l++)
                    acc[l] = fmaf(w[j], xw[5 + l - j], acc[l]);
            #pragma unroll
            for (int l = 0; l < 8; l++) pw[lane * 9 + l] = acc[l];
            __syncwarp();
            float v = 0.0f;
            #pragma unroll
            for (int j = 0; j < 8; j++) v += pw[(8 * q + j) * 9 + lq];
            v += __shfl_xor_sync(0xffffffffu, v, 8);
            v += __shfl_xor_sync(0xffffffffu, v, 16);
            if (lane < 8) sm[HB0 + ((kc + 1) & 1) * 136 + lane * 17 + s] = v;
        }
    } else {
        for (int kc = 0; kc < NCH; kc++) __syncthreads();
    }
}

extern "C" void kernel_launch(void* const* d_in, const int* in_sizes, int n_in,
                              void* d_out, int out_size)
{
    const float* S_e     = (const float*)d_in[0];
    const float* S_i     = (const float*)d_in[1];
    const float* C_den   = (const float*)d_in[2];
    const float* C_syn_e = (const float*)d_in[3];
    const float* C_syn_i = (const float*)d_in[4];
    const float* Tau_e   = (const float*)d_in[5];
    const float* Tau_i   = (const float*)d_in[6];
    const float* W_e     = (const float*)d_in[7];
    const float* W_i     = (const float*)d_in[8];
    const float* D_e     = (const float*)d_in[9];
    const float* D_i     = (const float*)d_in[10];
    const float* Tau_spk = (const float*)d_in[11];
    const float* W_spk   = (const float*)d_in[12];
    const float* W_hist  = (const float*)d_in[13];
    const float* Theta   = (const float*)d_in[14];
    float* out = (float*)d_out;

    cudaFuncSetAttribute(k_scan, cudaFuncAttributeMaxDynamicSharedMemorySize,
                         SMF * 4);
    k_prep<<<1, 256>>>(C_syn_e, C_syn_i, C_den, Tau_e, Tau_i, W_e, W_i,
                       D_e, D_i, Tau_spk, W_spk, W_hist,
                       out + (size_t)TD * SUB);
    k_syn<<<TD, 128>>>(S_e, S_i);
    k_conv<<<(TD + CTL - 1) / CTL, 256>>>(Theta);
    k_scan<<<1, 640, SMF * 4>>>(out);
}

// round 9
// speedup vs baseline: 6.9948x; 1.0616x over previous
#include <cuda_runtime.h>

#define T_NO 200
#define SUB  16
#define E_NO 2000
#define I_NO 500
#define TD   20000
#define CB   16
#define NCH  2500          // TD/8 chunks

#define PADT 256
#define TDP  (TD + PADT)
#define CT2  2048          // t-span per conv block

// smem layout (floats) for k_scan
#define RING0 0            // 16 rows x 513
#define LUT0  8208         // 2 x 256 x 16
#define PART0 16400        // 16 warps x 288
#define HB0   21008        // 2 x 8 x 17
#define SMF   21280

__device__ float g_eT[SUB * TDP];     // pooled e counts, [s][PADT+t], pad=0
__device__ float g_iT[SUB * TDP];
__device__ float g_syn[TD * SUB];     // conv + Theta folded, [t][s]
__device__ int   g_asn_e[E_NO];
__device__ int   g_asn_i[I_NO];
__device__ float g_ek[SUB * T_NO];
__device__ float g_ik[SUB * T_NO];
__device__ float g_sk[SUB * T_NO];
__device__ float g_hk[SUB * T_NO];
__device__ float g_B[SUB * SUB];      // C_den * A_k * r_k  (IIR injection)
__device__ float g_spkc[3 * SUB];     // r, 2r, -r^2

__global__ void k_prep(const float* __restrict__ C_syn_e,
                       const float* __restrict__ C_syn_i,
                       const float* __restrict__ C_den,
                       const float* __restrict__ Te, const float* __restrict__ Ti,
                       const float* __restrict__ We, const float* __restrict__ Wi,
                       const float* __restrict__ De, const float* __restrict__ Di,
                       const float* __restrict__ Tspk, const float* __restrict__ Wspk,
                       const float* __restrict__ Whist,
                       float* __restrict__ out_filt)
{
    int tid = threadIdx.x;
    for (int e = tid; e < E_NO; e += blockDim.x) {
        int a = 0;
        for (int s = 0; s < SUB; s++)
            if (C_syn_e[s * E_NO + e] > 0.5f) a = s;
        g_asn_e[e] = a;
    }
    for (int i = tid; i < I_NO; i += blockDim.x) {
        int a = 0;
        for (int s = 0; s < SUB; s++)
            if (C_syn_i[s * I_NO + i] > 0.5f) a = s;
        g_asn_i[i] = a;
    }
    for (int s = tid; s < SUB; s += blockDim.x) {
        float r = expf(-1.0f / expf(Tspk[s]));
        g_spkc[s] = r; g_spkc[SUB + s] = 2.0f * r; g_spkc[2 * SUB + s] = -r * r;
    }
    for (int idx = tid; idx < SUB * SUB; idx += blockDim.x) {
        int k = idx & 15;
        float r = expf(-1.0f / expf(Tspk[k]));
        g_B[idx] = C_den[idx] * expf(Wspk[k] - Tspk[k]) * r;
    }
    const float PI = 3.14159265358979323846f;
    for (int idx = tid; idx < SUB * T_NO; idx += blockDim.x) {
        int s = idx / T_NO, tau = idx % T_NO;
        float t = (float)tau;
        float te  = fmaxf(t - expf(De[s]), 0.0f);
        float tte = te / expf(Te[s]);
        float ek  = tte * expf(-tte) * expf(We[s]);
        float ti_ = fmaxf(t - expf(Di[s]), 0.0f);
        float tti = ti_ / expf(Ti[s]);
        float ik  = -tti * expf(-tti) * expf(Wi[s]);
        float tts = t / expf(Tspk[s]);
        float sk  = tts * expf(-tts) * expf(Wspk[s]);
        float raw = 4.0f * logf(t + 1.0f);
        float hk  = 0.0f;
        for (int b = 0; b < CB; b++) {
            float phi = (PI * 0.5f) * (float)b;
            float v   = 0.5f * cosf(raw - phi) + 0.5f;
            if (raw < phi - PI || raw > phi + PI) v = 0.0f;
            hk += Whist[s * CB + b] * v;
        }
        g_ek[idx] = ek; g_ik[idx] = ik; g_sk[idx] = sk; g_hk[idx] = hk;
        out_filt[(s)      * T_NO + tau] = ek;
        out_filt[(16 + s) * T_NO + tau] = ik;
        out_filt[(32 + s) * T_NO + tau] = sk;
        out_filt[(48 + s) * T_NO + tau] = hk;
    }
}

__global__ void k_syn(const float* __restrict__ Se, const float* __restrict__ Si)
{
    __shared__ float be[SUB], bi[SUB];
    int t = blockIdx.x, tid = threadIdx.x;
    if (tid < SUB) { be[tid] = 0.0f; bi[tid] = 0.0f; }
    __syncthreads();
    for (int e = tid; e < E_NO; e += blockDim.x) {
        float v = Se[(size_t)t * E_NO + e];
        if (v != 0.0f) atomicAdd(&be[g_asn_e[e]], v);
    }
    for (int i = tid; i < I_NO; i += blockDim.x) {
        float v = Si[(size_t)t * I_NO + i];
        if (v != 0.0f) atomicAdd(&bi[g_asn_i[i]], v);
    }
    __syncthreads();
    if (tid < SUB) {
        g_eT[tid * TDP + PADT + t] = be[tid];
        g_iT[tid * TDP + PADT + t] = bi[tid];
    }
}

// conv v2: transposed smem-staged FIR. Block = 256 threads, one subunit,
// 2048 consecutive t (8 per thread). 8-register circular window, static
// (p+l)&7 indices -> zero rotation MOVs. Per tap: 2 window LDS + 16 FMA.
__global__ void __launch_bounds__(256) k_conv(const float* __restrict__ Theta)
{
    __shared__ float se[2256], si[2256];
    __shared__ float ke[T_NO], ki[T_NO];
    int s = blockIdx.y;
    int tbase = blockIdx.x * CT2;
    int tid = threadIdx.x;

    for (int i = tid; i < T_NO; i += 256) {
        ke[i] = g_ek[s * T_NO + i];
        ki[i] = g_ik[s * T_NO + i];
    }
    // se[i] = syn_e(tbase-200+i); pad region of g_eT supplies zeros for t<0
    const float* ge = &g_eT[s * TDP + PADT + tbase - 200];
    const float* gi = &g_iT[s * TDP + PADT + tbase - 200];
    int limit = TD - tbase + 200;           // valid window length
    for (int i = tid; i < 2256; i += 256) {
        bool ok = (i < limit);
        se[i] = ok ? __ldg(&ge[i]) : 0.0f;
        si[i] = ok ? __ldg(&gi[i]) : 0.0f;
    }
    __syncthreads();

    int t0 = tbase + tid * 8;
    if (t0 >= TD) return;
    float th = Theta[s];
    float acc[8];
    #pragma unroll
    for (int l = 0; l < 8; l++) acc[l] = th;

    int base = tid * 8;                      // se index of syn(t0-200)
    float we[8], wi[8];
    #pragma unroll
    for (int l = 0; l < 8; l++) { we[l] = se[base + l]; wi[l] = si[base + l]; }

    // tap j = 0..199  <=>  lag d = 200-j, coeff k[199-j]
    for (int jb = 0; jb < 25; jb++) {
        #pragma unroll
        for (int p = 0; p < 8; p++) {
            int j = jb * 8 + p;
            float ce = ke[199 - j], ci = ki[199 - j];
            #pragma unroll
            for (int l = 0; l < 8; l++) {
                acc[l] = fmaf(ce, we[(p + l) & 7], acc[l]);
                acc[l] = fmaf(ci, wi[(p + l) & 7], acc[l]);
            }
            we[p] = se[base + j + 8];
            wi[p] = si[base + j + 8];
        }
    }
    #pragma unroll
    for (int l = 0; l < 8; l++)
        if (t0 + l < TD) g_syn[(t0 + l) * SUB + s] = acc[l];
}

// chunked scan (R8 design, refined): chunk=8, ONE barrier per chunk.
// conductor: hist d=1..15 via shift-free static fb[], spk path = collapsed
// 2-state IIR + mask-LUT injection (2-step slack). 16 helpers: d=16..200 for
// NEXT chunk, 6 consecutive taps/lane, smem-transpose reduce.
__global__ void __launch_bounds__(640, 1) k_scan(float* __restrict__ out)
{
    extern __shared__ float sm[];
    int tid = threadIdx.x, wid = tid >> 5, lane = tid & 31;

    for (int i = tid; i < SMF; i += blockDim.x) sm[i] = 0.0f;
    __syncthreads();
    for (int idx = tid; idx < 8192; idx += blockDim.x) {
        int m = (idx >> 4) & 255, s = idx & 15, h = idx >> 12;
        float v = 0.0f;
        #pragma unroll
        for (int b = 0; b < 8; b++)
            if ((m >> b) & 1) v += g_B[s * SUB + 8 * h + b];
        sm[LUT0 + idx] = v;
    }

    if (wid == 0) {
        // ------------- conductor -------------
        int s = lane & 15;
        float hkr[15];
        #pragma unroll
        for (int i = 0; i < 15; i++) hkr[i] = g_hk[s * T_NO + i];
        float twor = g_spkc[SUB + s], nr2 = g_spkc[2 * SUB + s];
        float carry[15];
        #pragma unroll
        for (int i = 0; i < 15; i++) carry[i] = 0.0f;
        float z0 = 0.f, z1 = 0.f, lutA = 0.f, lutB = 0.f;
        float cur[8], nxt[8];
        #pragma unroll
        for (int l = 0; l < 8; l++) cur[l] = __ldg(&g_syn[l * SUB + s]);
        float* ringw = sm + RING0 + s * 513;
        const float* lut = sm + LUT0;

        for (int kc = 0; kc < NCH; kc++) {
            __syncthreads();
            int t0 = kc * 8, c0 = t0 & 255;
            const float* hrow = sm + HB0 + (kc & 1) * 136;
            float K[8];
            #pragma unroll
            for (int l = 0; l < 8; l++) K[l] = hrow[l * 17 + s] + cur[l];
            #pragma unroll
            for (int l = 0; l < 8; l++) {
                int tn = t0 + 8 + l;
                nxt[l] = (tn < TD) ? __ldg(&g_syn[tn * SUB + s]) : 0.0f;
            }
            float fb[23];
            #pragma unroll
            for (int i = 0; i < 15; i++) fb[i] = carry[i];
            #pragma unroll
            for (int l = 0; l < 8; l++) {
                float zn = fmaf(twor, z1, fmaf(nr2, z0, lutA));
                z0 = z1; z1 = zn; lutA = lutB;
                float P = 0.0f;
                #pragma unroll
                for (int j = 2; j <= 15; j++)
                    P = fmaf(hkr[j - 1], fb[15 + l - j], P);
                float A = fmaf(hkr[0], fb[14 + l], P);
                float acc = (A + K[l]) + zn;
                bool pr = acc > 0.0f;
                unsigned mm = __ballot_sync(0xffffffffu, pr) & 0xFFFFu;
                float spkf = pr ? 1.0f : 0.0f;
                if (lane < 16) {
                    int c = c0 + l;
                    ringw[c] = spkf; ringw[c + 256] = spkf;
                    out[(t0 + l) * SUB + s] = spkf;
                }
                lutB = lut[(mm & 255u) * 16 + s] + lut[4096 + (mm >> 8) * 16 + s];
                fb[15 + l] = spkf;
            }
            #pragma unroll
            for (int i = 0; i < 15; i++) carry[i] = fb[8 + i];
            #pragma unroll
            for (int l = 0; l < 8; l++) cur[l] = nxt[l];
        }
    } else if (wid != 8 && wid != 12 && wid != 16) {
        // ------------- helpers: hist d = 16..200 for next chunk -------------
        int s = wid - 1 - (wid > 8) - (wid > 12) - (wid > 16);
        int d0 = 16 + 6 * lane;
        float w[6];
        #pragma unroll
        for (int j = 0; j < 6; j++) {
            int d = d0 + j;
            w[j] = (d <= T_NO) ? g_hk[s * T_NO + d - 1] : 0.0f;
        }
        const float* ringr = sm + RING0 + s * 513;
        float* pw = sm + PART0 + s * 288;
        int lq = lane & 7, q = lane >> 3;

        for (int kc = 0; kc < NCH; kc++) {
            __syncthreads();
            int t1 = kc * 8 + 8;
            int a0 = 256 + (t1 & 255) - d0 - 5;
            float xw[13];
            #pragma unroll
            for (int i = 0; i < 13; i++) xw[i] = ringr[a0 + i];
            float acc[8];
            #pragma unroll
            for (int l = 0; l < 8; l++) acc[l] = 0.0f;
            #pragma unroll
            for (int j = 0; j < 6; j++)
                #pragma unroll
                for (int l = 0; l < 8; l++)
                    acc[l] = fmaf(w[j], xw[5 + l - j], acc[l]);
            #pragma unroll
            for (int l = 0; l < 8; l++) pw[lane * 9 + l] = acc[l];
            __syncwarp();
            float v = 0.0f;
            #pragma unroll
            for (int j = 0; j < 8; j++) v += pw[(8 * q + j) * 9 + lq];
            v += __shfl_xor_sync(0xffffffffu, v, 8);
            v += __shfl_xor_sync(0xffffffffu, v, 16);
            if (lane < 8) sm[HB0 + ((kc + 1) & 1) * 136 + lane * 17 + s] = v;
        }
    } else {
        for (int kc = 0; kc < NCH; kc++) __syncthreads();
    }
}

extern "C" void kernel_launch(void* const* d_in, const int* in_sizes, int n_in,
                              void* d_out, int out_size)
{
    const float* S_e     = (const float*)d_in[0];
    const float* S_i     = (const float*)d_in[1];
    const float* C_den   = (const float*)d_in[2];
    const float* C_syn_e = (const float*)d_in[3];
    const float* C_syn_i = (const float*)d_in[4];
    const float* Tau_e   = (const float*)d_in[5];
    const float* Tau_i   = (const float*)d_in[6];
    const float* W_e     = (const float*)d_in[7];
    const float* W_i     = (const float*)d_in[8];
    const float* D_e     = (const float*)d_in[9];
    const float* D_i     = (const float*)d_in[10];
    const float* Tau_spk = (const float*)d_in[11];
    const float* W_spk   = (const float*)d_in[12];
    const float* W_hist  = (const float*)d_in[13];
    const float* Theta   = (const float*)d_in[14];
    float* out = (float*)d_out;

    cudaFuncSetAttribute(k_scan, cudaFuncAttributeMaxDynamicSharedMemorySize,
                         SMF * 4);
    k_prep<<<1, 256>>>(C_syn_e, C_syn_i, C_den, Tau_e, Tau_i, W_e, W_i,
                       D_e, D_i, Tau_spk, W_spk, W_hist,
                       out + (size_t)TD * SUB);
    k_syn<<<TD, 128>>>(S_e, S_i);
    dim3 cgrid((TD + CT2 - 1) / CT2, SUB);
    k_conv<<<cgrid, 256>>>(Theta);
    k_scan<<<1, 640, SMF * 4>>>(out);
}